// round 13
// baseline (speedup 1.0000x reference)
#include <cuda_runtime.h>
#include <cuda_bf16.h>
#include <cstdint>

// Problem constants
#define BATCH 4
#define SEQ   2048
#define DMODEL 1024
#define NHEADS 16
#define DK 64
#define TOKENS (BATCH*SEQ)          // 8192
#define NQKV   (3*NHEADS*DK)        // 3072

// ---------------------------------------------------------------------------
// Scratch (device globals — allocation-free)
// ---------------------------------------------------------------------------
__device__ __align__(16) __nv_bfloat16 g_xh[(size_t)TOKENS*DMODEL];
__device__ __align__(16) __nv_bfloat16 g_xl[(size_t)TOKENS*DMODEL];
__device__ __align__(16) __nv_bfloat16 g_hh[(size_t)TOKENS*DMODEL];   // heads split
__device__ __align__(16) __nv_bfloat16 g_hl[(size_t)TOKENS*DMODEL];
__device__ __align__(16) __nv_bfloat16 g_Bqh[(size_t)NQKV*DMODEL];
__device__ __align__(16) __nv_bfloat16 g_Bql[(size_t)NQKV*DMODEL];
__device__ __align__(16) __nv_bfloat16 g_Bwh[(size_t)DMODEL*DMODEL];
__device__ __align__(16) __nv_bfloat16 g_Bwl[(size_t)DMODEL*DMODEL];
// Q/K/V split bf16 in [b,h,s,d]
__device__ __align__(16) __nv_bfloat16 g_Qh[(size_t)TOKENS*DMODEL];
__device__ __align__(16) __nv_bfloat16 g_Ql[(size_t)TOKENS*DMODEL];
__device__ __align__(16) __nv_bfloat16 g_Kh[(size_t)TOKENS*DMODEL];
__device__ __align__(16) __nv_bfloat16 g_Kl[(size_t)TOKENS*DMODEL];
__device__ __align__(16) __nv_bfloat16 g_Vh[(size_t)TOKENS*DMODEL];
__device__ __align__(16) __nv_bfloat16 g_Vl[(size_t)TOKENS*DMODEL];

// ---------------------------------------------------------------------------
// MMA helpers (base compute_103: mma.sync / ldmatrix / cp.async)
// ---------------------------------------------------------------------------
__device__ __forceinline__ uint32_t smem_u32(const void* p) {
    uint32_t a;
    asm("{ .reg .u64 t; cvta.to.shared.u64 t, %1; cvt.u32.u64 %0, t; }" : "=r"(a) : "l"(p));
    return a;
}
#define LDMATRIX_X4(r, addr) \
    asm volatile("ldmatrix.sync.aligned.m8n8.x4.shared.b16 {%0,%1,%2,%3}, [%4];" \
        : "=r"((r)[0]), "=r"((r)[1]), "=r"((r)[2]), "=r"((r)[3]) : "r"(addr))
#define LDMATRIX_X4_TRANS(r, addr) \
    asm volatile("ldmatrix.sync.aligned.m8n8.x4.trans.shared.b16 {%0,%1,%2,%3}, [%4];" \
        : "=r"((r)[0]), "=r"((r)[1]), "=r"((r)[2]), "=r"((r)[3]) : "r"(addr))
#define MMA16816(d, a, b0, b1) \
    asm volatile("mma.sync.aligned.m16n8k16.row.col.f32.bf16.bf16.f32 " \
        "{%0,%1,%2,%3}, {%4,%5,%6,%7}, {%8,%9}, {%0,%1,%2,%3};" \
        : "+f"((d)[0]), "+f"((d)[1]), "+f"((d)[2]), "+f"((d)[3]) \
        : "r"((a)[0]), "r"((a)[1]), "r"((a)[2]), "r"((a)[3]), "r"(b0), "r"(b1))
#define CP_ASYNC16(smaddr, gptr) \
    asm volatile("cp.async.cg.shared.global [%0], [%1], 16;" :: "r"(smaddr), "l"(gptr))
#define CP_COMMIT() asm volatile("cp.async.commit_group;" ::: "memory")
#define CP_WAIT2()  asm volatile("cp.async.wait_group 2;" ::: "memory")
#define CP_WAIT1()  asm volatile("cp.async.wait_group 1;" ::: "memory")
#define CP_WAIT0()  asm volatile("cp.async.wait_group 0;" ::: "memory")

__device__ __forceinline__ float ex2f(float x) {
    float y; asm("ex2.approx.f32 %0, %1;" : "=f"(y) : "f"(x)); return y;
}
// split two fp32 into bf16x2 hi/lo pairs (low half = first element)
__device__ __forceinline__ void split_pack2(float a, float b, uint32_t& hi, uint32_t& lo) {
    __nv_bfloat162 h = __floats2bfloat162_rn(a, b);
    float ra = a - __bfloat162float(h.x);
    float rb = b - __bfloat162float(h.y);
    __nv_bfloat162 l = __floats2bfloat162_rn(ra, rb);
    hi = *(uint32_t*)&h;
    lo = *(uint32_t*)&l;
}

// ---------------------------------------------------------------------------
// Split fp32 -> (bf16 hi, bf16 lo), vectorized x4
// ---------------------------------------------------------------------------
__global__ __launch_bounds__(256) void split_f32_kernel(
    const float* __restrict__ in, __nv_bfloat16* __restrict__ hi,
    __nv_bfloat16* __restrict__ lo, int n4)
{
    int i = blockIdx.x * 256 + threadIdx.x;
    if (i >= n4) return;
    float4 v = ((const float4*)in)[i];
    uint32_t h0, l0, h1, l1;
    split_pack2(v.x, v.y, h0, l0);
    split_pack2(v.z, v.w, h1, l1);
    uint32_t* H = (uint32_t*)hi;
    uint32_t* L = (uint32_t*)lo;
    H[2*i]   = h0;  H[2*i+1] = h1;
    L[2*i]   = l0;  L[2*i+1] = l1;
}

// ---------------------------------------------------------------------------
// QKV weight conversion: W[h][d][k] -> B[n][d], split
// ---------------------------------------------------------------------------
__global__ __launch_bounds__(256) void conv_wqkv_kernel(
    const float* __restrict__ Wq, const float* __restrict__ Wk, const float* __restrict__ Wv,
    __nv_bfloat16* __restrict__ Bh, __nv_bfloat16* __restrict__ Bl)
{
    const int bx = blockIdx.x;
    const int which = bx >> 8;
    const int h = (bx >> 4) & 15;
    const int d0 = (bx & 15) * 64;
    const float* W = (which == 0) ? Wq : (which == 1) ? Wk : Wv;
    __shared__ float tile[64][65];
    const int tid = threadIdx.x;
    #pragma unroll
    for (int it = 0; it < 16; it++) {
        int r = it * 4 + (tid >> 6);
        int c = tid & 63;
        tile[r][c] = W[((size_t)h * 1024 + d0 + r) * 64 + c];
    }
    __syncthreads();
    #pragma unroll
    for (int it = 0; it < 16; it++) {
        int cc = it * 4 + (tid >> 6);
        int dd = tid & 63;
        float v = tile[dd][cc];
        __nv_bfloat16 hh = __float2bfloat16(v);
        __nv_bfloat16 ll = __float2bfloat16(v - __bfloat162float(hh));
        size_t n = (size_t)which * 1024 + h * 64 + cc;
        Bh[n * 1024 + d0 + dd] = hh;
        Bl[n * 1024 + d0 + dd] = ll;
    }
}

// Wo conversion: Wo[k][n] -> B[n][k], split.
__global__ __launch_bounds__(256) void conv_wo_kernel(
    const float* __restrict__ Wo, __nv_bfloat16* __restrict__ Bh, __nv_bfloat16* __restrict__ Bl)
{
    const int bx = blockIdx.x;
    const int k0 = (bx & 15) * 64;
    const int n0 = (bx >> 4) * 64;
    __shared__ float tile[64][65];
    const int tid = threadIdx.x;
    #pragma unroll
    for (int it = 0; it < 16; it++) {
        int r = it * 4 + (tid >> 6);
        int c = tid & 63;
        tile[r][c] = Wo[(size_t)(k0 + r) * 1024 + n0 + c];
    }
    __syncthreads();
    #pragma unroll
    for (int it = 0; it < 16; it++) {
        int cc = it * 4 + (tid >> 6);
        int dd = tid & 63;
        float v = tile[dd][cc];
        __nv_bfloat16 hh = __float2bfloat16(v);
        __nv_bfloat16 ll = __float2bfloat16(v - __bfloat162float(hh));
        Bh[(size_t)(n0 + cc) * 1024 + k0 + dd] = hh;
        Bl[(size_t)(n0 + cc) * 1024 + k0 + dd] = ll;
    }
}

// ---------------------------------------------------------------------------
// mma.sync split-bf16 GEMM (R10 version — unchanged, best known: 503us).
// block 128x128x32, 128 threads / 4 warps (2x2), 2 CTAs/SM.
// ---------------------------------------------------------------------------
#define BM 128
#define BN 128
#define BK 32
#define PADK 40
#define ARR_BYTES (128 * PADK * 2)           // 10240
#define STAGE_BYTES (4 * ARR_BYTES)          // 40960: Ah | Al | Bh | Bl
#define GEMM_SMEM (2 * STAGE_BYTES)          // 81920 -> 2 CTAs/SM

template<int MODE>
__global__ __launch_bounds__(128, 2) void gemm_mma_kernel(
    const __nv_bfloat16* __restrict__ Ah_g, const __nv_bfloat16* __restrict__ Al_g,
    const __nv_bfloat16* __restrict__ Bh_g, const __nv_bfloat16* __restrict__ Bl_g,
    float* __restrict__ out)
{
    extern __shared__ char smc[];
    const int tid = threadIdx.x;
    const int lane = tid & 31;
    const int warp = tid >> 5;       // 0..3
    const int wm = warp >> 1;        // 0..1 -> 64-row band
    const int wn = warp & 1;         // 0..1 -> 64-col band
    const int n0 = blockIdx.x * BN;
    const int t0 = blockIdx.y * BM;
    const uint32_t smem_base = smem_u32(smc);

    auto prefetch = [&](int s, int k0) {
        const uint32_t sbase = smem_base + s * STAGE_BYTES;
        #pragma unroll
        for (int i = 0; i < 16; i++) {
            const int cid = i * 128 + tid;
            const int arr = cid >> 9;
            const int idx = cid & 511;
            const int row = idx >> 2;
            const int c16 = idx & 3;
            const __nv_bfloat16* g;
            if      (arr == 0) g = Ah_g + (size_t)(t0 + row) * DMODEL + k0 + c16 * 8;
            else if (arr == 1) g = Al_g + (size_t)(t0 + row) * DMODEL + k0 + c16 * 8;
            else if (arr == 2) g = Bh_g + (size_t)(n0 + row) * DMODEL + k0 + c16 * 8;
            else               g = Bl_g + (size_t)(n0 + row) * DMODEL + k0 + c16 * 8;
            const uint32_t sa = sbase + arr * ARR_BYTES + (row * PADK + c16 * 8) * 2;
            CP_ASYNC16(sa, g);
        }
        CP_COMMIT();
    };

    float acc[4][8][4];
    #pragma unroll
    for (int i = 0; i < 4; i++)
        #pragma unroll
        for (int j = 0; j < 8; j++)
            #pragma unroll
            for (int q = 0; q < 4; q++) acc[i][j][q] = 0.0f;

    prefetch(0, 0);

    const int r_in = lane & 15;
    const int khalf = (lane >> 4) * 8;

    for (int kt = 0; kt < DMODEL / BK; kt++) {
        if (kt < DMODEL / BK - 1) { prefetch((kt + 1) & 1, (kt + 1) * BK); CP_WAIT1(); }
        else CP_WAIT0();
        __syncthreads();

        const uint32_t sbase = smem_base + (kt & 1) * STAGE_BYTES;
        const uint32_t aH = sbase;
        const uint32_t aL = sbase + ARR_BYTES;
        const uint32_t bH = sbase + 2 * ARR_BYTES;
        const uint32_t bL = sbase + 3 * ARR_BYTES;

        #pragma unroll
        for (int kk = 0; kk < BK; kk += 16) {
            uint32_t ah[4][4], al[4][4];
            #pragma unroll
            for (int mt = 0; mt < 4; mt++) {
                const uint32_t off = ((wm * 64 + mt * 16 + r_in) * PADK + kk + khalf) * 2;
                LDMATRIX_X4(ah[mt], aH + off);
                LDMATRIX_X4(al[mt], aL + off);
            }
            #pragma unroll
            for (int ng = 0; ng < 4; ng++) {
                uint32_t bh[4], bl[4];
                const uint32_t off = ((wn * 64 + ng * 16 + r_in) * PADK + kk + khalf) * 2;
                LDMATRIX_X4(bh, bH + off);
                LDMATRIX_X4(bl, bL + off);
                #pragma unroll
                for (int mt = 0; mt < 4; mt++) {
                    #pragma unroll
                    for (int sel = 0; sel < 2; sel++) {
                        const int nt = ng * 2 + sel;
                        MMA16816(acc[mt][nt], ah[mt], bh[sel], bh[sel + 2]);
                        MMA16816(acc[mt][nt], ah[mt], bl[sel], bl[sel + 2]);
                        MMA16816(acc[mt][nt], al[mt], bh[sel], bh[sel + 2]);
                    }
                }
            }
        }
        __syncthreads();
    }

    const int qr = lane >> 2;
    const int qc = (lane & 3) * 2;
    if (MODE == 1) {
        #pragma unroll
        for (int mt = 0; mt < 4; mt++) {
            const int r1 = t0 + wm * 64 + mt * 16 + qr;
            #pragma unroll
            for (int nt = 0; nt < 8; nt++) {
                const int nb = n0 + wn * 64 + nt * 8 + qc;
                *(float2*)&out[(size_t)r1 * DMODEL + nb]       = make_float2(acc[mt][nt][0], acc[mt][nt][1]);
                *(float2*)&out[(size_t)(r1 + 8) * DMODEL + nb] = make_float2(acc[mt][nt][2], acc[mt][nt][3]);
            }
        }
    } else {
        const int bb = t0 >> 11;
        const int s_base = t0 & 2047;
        #pragma unroll
        for (int nt = 0; nt < 8; nt++) {
            const int nb = n0 + wn * 64 + nt * 8;
            const int which = nb >> 10;
            const int rem = nb & 1023;
            const int h = rem >> 6;
            const int k2 = (rem & 63) + qc;
            __nv_bfloat16 *dh, *dl;
            if      (which == 0) { dh = g_Qh; dl = g_Ql; }
            else if (which == 1) { dh = g_Kh; dl = g_Kl; }
            else                 { dh = g_Vh; dl = g_Vl; }
            const size_t hb = (((size_t)bb * NHEADS + h) * SEQ) * DK + k2;
            #pragma unroll
            for (int mt = 0; mt < 4; mt++) {
                const int s1 = s_base + wm * 64 + mt * 16 + qr;
                uint32_t h0, l0, h1, l1;
                split_pack2(acc[mt][nt][0], acc[mt][nt][1], h0, l0);
                split_pack2(acc[mt][nt][2], acc[mt][nt][3], h1, l1);
                *(uint32_t*)&dh[hb + (size_t)s1 * DK]       = h0;
                *(uint32_t*)&dl[hb + (size_t)s1 * DK]       = l0;
                *(uint32_t*)&dh[hb + (size_t)(s1 + 8) * DK] = h1;
                *(uint32_t*)&dl[hb + (size_t)(s1 + 8) * DK] = l1;
            }
        }
    }
}

// ---------------------------------------------------------------------------
// Flash attention via mma.sync split-bf16, SOFTWARE-PIPELINED:
// per iteration: QK(kt+1) -> PV(kt) (tensor back-to-back) -> softmax(kt+1)
// -> merge. Double sacc registers, 3 KV smem stages.
// ---------------------------------------------------------------------------
#define BQ 128
#define BKV 64
#define QSTR 72                              // smem row stride (bf16)
#define Q_ARR  (BQ * QSTR * 2)               // 18432
#define KV_ARR (BKV * QSTR * 2)              // 9216
#define KV_STAGE (4 * KV_ARR)                // 36864 : Kh | Kl | Vh | Vl
#define KV_STAGES 3
#define ATTN_SMEM (2 * Q_ARR + KV_STAGES * KV_STAGE)   // 147456

// QK MMAs for tile KT into sacc[SIDX]
#define QK_MMA(SIDX, KT) do { \
    const uint32_t stg_ = kvbase + ((KT) % 3) * (uint32_t)KV_STAGE; \
    _Pragma("unroll") \
    for (int t_ = 0; t_ < 8; t_++) \
        _Pragma("unroll") \
        for (int q_ = 0; q_ < 4; q_++) sacc[SIDX][t_][q_] = 0.0f; \
    _Pragma("unroll") \
    for (int ng = 0; ng < 4; ng++) { \
        _Pragma("unroll") \
        for (int kc = 0; kc < 4; kc++) { \
            uint32_t khf[4], klf[4]; \
            const uint32_t off = ((ng * 16 + r_in) * QSTR + kc * 16 + khalf) * 2; \
            LDMATRIX_X4(khf, stg_ + off); \
            LDMATRIX_X4(klf, stg_ + KV_ARR + off); \
            _Pragma("unroll") \
            for (int sel = 0; sel < 2; sel++) { \
                const int t_ = ng * 2 + sel; \
                MMA16816(sacc[SIDX][t_], qhf[kc], khf[sel], khf[sel + 2]); \
                MMA16816(sacc[SIDX][t_], qhf[kc], klf[sel], klf[sel + 2]); \
                MMA16816(sacc[SIDX][t_], qlf[kc], khf[sel], khf[sel + 2]); \
            } \
        } \
    } \
} while (0)

// PV MMAs for tile KT using sacc[SIDX] (already exp'd)
#define PV_STEP(SIDX, KT) do { \
    const uint32_t stg_ = kvbase + ((KT) % 3) * (uint32_t)KV_STAGE; \
    _Pragma("unroll") \
    for (int sc = 0; sc < 4; sc++) { \
        uint32_t phf[4], plf[4]; \
        split_pack2(sacc[SIDX][sc*2][0],   sacc[SIDX][sc*2][1],   phf[0], plf[0]); \
        split_pack2(sacc[SIDX][sc*2][2],   sacc[SIDX][sc*2][3],   phf[1], plf[1]); \
        split_pack2(sacc[SIDX][sc*2+1][0], sacc[SIDX][sc*2+1][1], phf[2], plf[2]); \
        split_pack2(sacc[SIDX][sc*2+1][2], sacc[SIDX][sc*2+1][3], phf[3], plf[3]); \
        _Pragma("unroll") \
        for (int dg = 0; dg < 4; dg++) { \
            uint32_t vhf[4], vlf[4]; \
            const uint32_t voff = ((sc * 16 + r_in) * QSTR + dg * 16 + khalf) * 2; \
            LDMATRIX_X4_TRANS(vhf, stg_ + 2 * KV_ARR + voff); \
            LDMATRIX_X4_TRANS(vlf, stg_ + 3 * KV_ARR + voff); \
            _Pragma("unroll") \
            for (int sel = 0; sel < 2; sel++) { \
                const int t_ = dg * 2 + sel; \
                MMA16816(oacc[t_], phf, vhf[2*sel], vhf[2*sel+1]); \
                MMA16816(oacc[t_], phf, vlf[2*sel], vlf[2*sel+1]); \
                MMA16816(oacc[t_], plf, vhf[2*sel], vhf[2*sel+1]); \
            } \
        } \
    } \
} while (0)

// softmax part-a on sacc[SIDX]: max/shfl, c, exp in place, row sums. Updates m.
#define PARTA(SIDX, C0V, C1V, S0V, S1V) do { \
    float mx0 = -1e30f, mx1 = -1e30f; \
    _Pragma("unroll") \
    for (int t_ = 0; t_ < 8; t_++) { \
        mx0 = fmaxf(mx0, fmaxf(sacc[SIDX][t_][0], sacc[SIDX][t_][1])); \
        mx1 = fmaxf(mx1, fmaxf(sacc[SIDX][t_][2], sacc[SIDX][t_][3])); \
    } \
    mx0 *= scale2; mx1 *= scale2; \
    mx0 = fmaxf(mx0, __shfl_xor_sync(0xffffffffu, mx0, 1)); \
    mx0 = fmaxf(mx0, __shfl_xor_sync(0xffffffffu, mx0, 2)); \
    mx1 = fmaxf(mx1, __shfl_xor_sync(0xffffffffu, mx1, 1)); \
    mx1 = fmaxf(mx1, __shfl_xor_sync(0xffffffffu, mx1, 2)); \
    const float nm0 = fmaxf(m0, mx0); \
    const float nm1 = fmaxf(m1, mx1); \
    C0V = ex2f(m0 - nm0); \
    C1V = ex2f(m1 - nm1); \
    m0 = nm0; m1 = nm1; \
    float s0_ = 0.0f, s1_ = 0.0f; \
    _Pragma("unroll") \
    for (int t_ = 0; t_ < 8; t_++) { \
        sacc[SIDX][t_][0] = ex2f(fmaf(sacc[SIDX][t_][0], scale2, -m0)); \
        sacc[SIDX][t_][1] = ex2f(fmaf(sacc[SIDX][t_][1], scale2, -m0)); \
        sacc[SIDX][t_][2] = ex2f(fmaf(sacc[SIDX][t_][2], scale2, -m1)); \
        sacc[SIDX][t_][3] = ex2f(fmaf(sacc[SIDX][t_][3], scale2, -m1)); \
        s0_ += sacc[SIDX][t_][0] + sacc[SIDX][t_][1]; \
        s1_ += sacc[SIDX][t_][2] + sacc[SIDX][t_][3]; \
    } \
    s0_ += __shfl_xor_sync(0xffffffffu, s0_, 1); \
    s0_ += __shfl_xor_sync(0xffffffffu, s0_, 2); \
    s1_ += __shfl_xor_sync(0xffffffffu, s1_, 1); \
    s1_ += __shfl_xor_sync(0xffffffffu, s1_, 2); \
    S0V = s0_; S1V = s1_; \
} while (0)

#define MERGE(C0V, C1V, S0V, S1V) do { \
    _Pragma("unroll") \
    for (int t_ = 0; t_ < 8; t_++) { \
        oacc[t_][0] *= C0V; oacc[t_][1] *= C0V; \
        oacc[t_][2] *= C1V; oacc[t_][3] *= C1V; \
    } \
    l0 = l0 * C0V + S0V; \
    l1 = l1 * C1V + S1V; \
} while (0)

__global__ __launch_bounds__(256) void attn_mma_kernel()
{
    extern __shared__ char smc[];
    const uint32_t sb = smem_u32(smc);
    const int tid = threadIdx.x;
    const int lane = tid & 31;
    const int w = tid >> 5;
    const int q0 = blockIdx.x * BQ;
    const int h = blockIdx.y;
    const int b = blockIdx.z;

    const size_t base = (((size_t)b * NHEADS + h) * SEQ) * DK;
    const __nv_bfloat16* Qh_g = g_Qh + base + (size_t)q0 * DK;
    const __nv_bfloat16* Ql_g = g_Ql + base + (size_t)q0 * DK;
    const __nv_bfloat16* Kh_g = g_Kh + base;
    const __nv_bfloat16* Kl_g = g_Kl + base;
    const __nv_bfloat16* Vh_g = g_Vh + base;
    const __nv_bfloat16* Vl_g = g_Vl + base;
    const uint32_t kvbase = sb + 2 * Q_ARR;

    // Q tile: 2048 16B-chunks (Qh|Ql), 8 per thread  -> group "Q"
    #pragma unroll
    for (int i = 0; i < 8; i++) {
        const int cid = i * 256 + tid;
        const int arr = cid >> 10;
        const int idx = cid & 1023;
        const int row = idx >> 3;
        const int c = (idx & 7) * 8;
        const __nv_bfloat16* g = (arr ? Ql_g : Qh_g) + (size_t)row * DK + c;
        CP_ASYNC16(sb + arr * Q_ARR + (row * QSTR + c) * 2, g);
    }
    CP_COMMIT();

    auto pref = [&](int kt) {
        const int s = kt % KV_STAGES;
        const int kv0 = kt * BKV;
        #pragma unroll
        for (int i = 0; i < 8; i++) {
            const int cid = i * 256 + tid;
            const int arr = cid >> 9;          // 0 Kh, 1 Kl, 2 Vh, 3 Vl
            const int idx = cid & 511;
            const int row = idx >> 3;
            const int c = (idx & 7) * 8;
            const __nv_bfloat16* g;
            if      (arr == 0) g = Kh_g;
            else if (arr == 1) g = Kl_g;
            else if (arr == 2) g = Vh_g;
            else               g = Vl_g;
            g += (size_t)(kv0 + row) * DK + c;
            CP_ASYNC16(kvbase + s * KV_STAGE + arr * KV_ARR + (row * QSTR + c) * 2, g);
        }
        CP_COMMIT();
    };
    pref(0); pref(1); pref(2);

    CP_WAIT2();          // Q + stage0 resident (stages 1,2 may be in flight)
    __syncthreads();

    const int r_in = lane & 15;
    const int khalf = (lane >> 4) * 8;
    const int qr = lane >> 2;
    const int qc = (lane & 3) * 2;

    // Q fragments, register-resident for entire loop
    uint32_t qhf[4][4], qlf[4][4];
    #pragma unroll
    for (int kc = 0; kc < 4; kc++) {
        const uint32_t off = ((w * 16 + r_in) * QSTR + kc * 16 + khalf) * 2;
        LDMATRIX_X4(qhf[kc], sb + off);
        LDMATRIX_X4(qlf[kc], sb + Q_ARR + off);
    }

    float oacc[8][4];
    #pragma unroll
    for (int t = 0; t < 8; t++)
        #pragma unroll
        for (int q = 0; q < 4; q++) oacc[t][q] = 0.0f;
    float m0 = -1e30f, m1 = -1e30f, l0 = 0.0f, l1 = 0.0f;
    float sacc[2][8][4];
    const float scale2 = 0.18033688011112042f;   // (1/8)*log2(e)
    const int NT = SEQ / BKV;   // 32

    // ---- preamble: tile 0 -> sacc[0], softmax(0); oacc=0 so merge is l=s ----
    float c0n, c1n, s0n, s1n;
    QK_MMA(0, 0);
    PARTA(0, c0n, c1n, s0n, s1n);
    l0 = s0n; l1 = s1n;          // l was 0; oacc*0 == 0

    // ---- pipelined main loop: process tile pairs ----
    #pragma unroll 1
    for (int ki = 0; ki < NT / 2; ki++) {
        const int kt0 = 2 * ki;
        // sub-iter A: QK(kt0+1)->sacc[1], PV(kt0) from sacc[0]
        {
            if (kt0 < NT - 2) CP_WAIT1(); else CP_WAIT0();
            __syncthreads();
            QK_MMA(1, kt0 + 1);
            PV_STEP(0, kt0);
            PARTA(1, c0n, c1n, s0n, s1n);
            __syncthreads();
            if (kt0 + 3 < NT) pref(kt0 + 3);
            MERGE(c0n, c1n, s0n, s1n);
        }
        // sub-iter B: kt1 = kt0+1
        {
            const int kt1 = kt0 + 1;
            if (kt1 + 1 < NT) {
                if (kt1 < NT - 2) CP_WAIT1(); else CP_WAIT0();
                __syncthreads();
                QK_MMA(0, kt1 + 1);
                PV_STEP(1, kt1);
                PARTA(0, c0n, c1n, s0n, s1n);
                __syncthreads();
                if (kt1 + 3 < NT) pref(kt1 + 3);
                MERGE(c0n, c1n, s0n, s1n);
            } else {
                // last tile: only PV remains (data long resident)
                PV_STEP(1, kt1);
            }
        }
    }

    // ---- epilogue: normalize, split, write heads [t][h*64+d] ----
    const float inv0 = 1.0f / l0;
    const float inv1 = 1.0f / l1;
    const size_t tg0 = (size_t)(b * SEQ + q0 + w * 16 + qr) * DMODEL + h * DK;
    const size_t tg1 = tg0 + (size_t)8 * DMODEL;
    #pragma unroll
    for (int t = 0; t < 8; t++) {
        const int col = t * 8 + qc;
        uint32_t h0, l0p, h1, l1p;
        split_pack2(oacc[t][0] * inv0, oacc[t][1] * inv0, h0, l0p);
        split_pack2(oacc[t][2] * inv1, oacc[t][3] * inv1, h1, l1p);
        *(uint32_t*)&g_hh[tg0 + col] = h0;
        *(uint32_t*)&g_hl[tg0 + col] = l0p;
        *(uint32_t*)&g_hh[tg1 + col] = h1;
        *(uint32_t*)&g_hl[tg1 + col] = l1p;
    }
}

// ---------------------------------------------------------------------------
extern "C" void kernel_launch(void* const* d_in, const int* in_sizes, int n_in,
                              void* d_out, int out_size)
{
    const float* x  = (const float*)d_in[0];
    const float* Wq = (const float*)d_in[1];
    const float* Wk = (const float*)d_in[2];
    const float* Wv = (const float*)d_in[3];
    const float* Wo = (const float*)d_in[4];
    float* out = (float*)d_out;

    __nv_bfloat16 *xh, *xl, *hh, *hl, *bqh, *bql, *bwh, *bwl;
    cudaGetSymbolAddress((void**)&xh,  g_xh);
    cudaGetSymbolAddress((void**)&xl,  g_xl);
    cudaGetSymbolAddress((void**)&hh,  g_hh);
    cudaGetSymbolAddress((void**)&hl,  g_hl);
    cudaGetSymbolAddress((void**)&bqh, g_Bqh);
    cudaGetSymbolAddress((void**)&bql, g_Bql);
    cudaGetSymbolAddress((void**)&bwh, g_Bwh);
    cudaGetSymbolAddress((void**)&bwl, g_Bwl);

    const int n4 = (TOKENS * DMODEL) / 4;

    // 1) Conversions
    split_f32_kernel<<<n4 / 256, 256>>>(x, xh, xl, n4);
    conv_wqkv_kernel<<<768, 256>>>(Wq, Wk, Wv, bqh, bql);
    conv_wo_kernel<<<256, 256>>>(Wo, bwh, bwl);

    // 2) QKV projection (epilogue emits split-bf16 Q/K/V)
    cudaFuncSetAttribute(gemm_mma_kernel<0>,
                         cudaFuncAttributeMaxDynamicSharedMemorySize, GEMM_SMEM);
    gemm_mma_kernel<0><<<dim3(NQKV / BN, TOKENS / BM), 128, GEMM_SMEM>>>(
        xh, xl, bqh, bql, nullptr);

    // 3) Flash attention on tensor cores (pipelined; writes heads pre-split)
    cudaFuncSetAttribute(attn_mma_kernel,
                         cudaFuncAttributeMaxDynamicSharedMemorySize, ATTN_SMEM);
    attn_mma_kernel<<<dim3(SEQ / BQ, NHEADS, BATCH), 256, ATTN_SMEM>>>();

    // 4) Output projection
    cudaFuncSetAttribute(gemm_mma_kernel<1>,
                         cudaFuncAttributeMaxDynamicSharedMemorySize, GEMM_SMEM);
    gemm_mma_kernel<1><<<dim3(DMODEL / BN, TOKENS / BM), 128, GEMM_SMEM>>>(
        hh, hl, bwh, bwl, out);
}

// round 16
// speedup vs baseline: 1.0174x; 1.0174x over previous
#include <cuda_runtime.h>
#include <cuda_bf16.h>
#include <cstdint>

// Problem constants
#define BATCH 4
#define SEQ   2048
#define DMODEL 1024
#define NHEADS 16
#define DK 64
#define TOKENS (BATCH*SEQ)          // 8192
#define NQKV   (3*NHEADS*DK)        // 3072

// ---------------------------------------------------------------------------
// Scratch (device globals — allocation-free)
// ---------------------------------------------------------------------------
__device__ __align__(16) __nv_bfloat16 g_xh[(size_t)TOKENS*DMODEL];
__device__ __align__(16) __nv_bfloat16 g_xl[(size_t)TOKENS*DMODEL];
__device__ __align__(16) __nv_bfloat16 g_hh[(size_t)TOKENS*DMODEL];   // heads split
__device__ __align__(16) __nv_bfloat16 g_hl[(size_t)TOKENS*DMODEL];
__device__ __align__(16) __nv_bfloat16 g_Bqh[(size_t)NQKV*DMODEL];
__device__ __align__(16) __nv_bfloat16 g_Bql[(size_t)NQKV*DMODEL];
__device__ __align__(16) __nv_bfloat16 g_Bwh[(size_t)DMODEL*DMODEL];
__device__ __align__(16) __nv_bfloat16 g_Bwl[(size_t)DMODEL*DMODEL];
// Q/K/V split bf16 in [b,h,s,d]
__device__ __align__(16) __nv_bfloat16 g_Qh[(size_t)TOKENS*DMODEL];
__device__ __align__(16) __nv_bfloat16 g_Ql[(size_t)TOKENS*DMODEL];
__device__ __align__(16) __nv_bfloat16 g_Kh[(size_t)TOKENS*DMODEL];
__device__ __align__(16) __nv_bfloat16 g_Kl[(size_t)TOKENS*DMODEL];
__device__ __align__(16) __nv_bfloat16 g_Vh[(size_t)TOKENS*DMODEL];
__device__ __align__(16) __nv_bfloat16 g_Vl[(size_t)TOKENS*DMODEL];

// ---------------------------------------------------------------------------
// MMA helpers (base compute_103: mma.sync / ldmatrix / cp.async)
// ---------------------------------------------------------------------------
__device__ __forceinline__ uint32_t smem_u32(const void* p) {
    uint32_t a;
    asm("{ .reg .u64 t; cvta.to.shared.u64 t, %1; cvt.u32.u64 %0, t; }" : "=r"(a) : "l"(p));
    return a;
}
#define LDMATRIX_X4(r, addr) \
    asm volatile("ldmatrix.sync.aligned.m8n8.x4.shared.b16 {%0,%1,%2,%3}, [%4];" \
        : "=r"((r)[0]), "=r"((r)[1]), "=r"((r)[2]), "=r"((r)[3]) : "r"(addr))
#define LDMATRIX_X4_TRANS(r, addr) \
    asm volatile("ldmatrix.sync.aligned.m8n8.x4.trans.shared.b16 {%0,%1,%2,%3}, [%4];" \
        : "=r"((r)[0]), "=r"((r)[1]), "=r"((r)[2]), "=r"((r)[3]) : "r"(addr))
#define MMA16816(d, a, b0, b1) \
    asm volatile("mma.sync.aligned.m16n8k16.row.col.f32.bf16.bf16.f32 " \
        "{%0,%1,%2,%3}, {%4,%5,%6,%7}, {%8,%9}, {%0,%1,%2,%3};" \
        : "+f"((d)[0]), "+f"((d)[1]), "+f"((d)[2]), "+f"((d)[3]) \
        : "r"((a)[0]), "r"((a)[1]), "r"((a)[2]), "r"((a)[3]), "r"(b0), "r"(b1))
#define CP_ASYNC16(smaddr, gptr) \
    asm volatile("cp.async.cg.shared.global [%0], [%1], 16;" :: "r"(smaddr), "l"(gptr))
#define CP_COMMIT() asm volatile("cp.async.commit_group;" ::: "memory")
#define CP_WAIT2()  asm volatile("cp.async.wait_group 2;" ::: "memory")
#define CP_WAIT1()  asm volatile("cp.async.wait_group 1;" ::: "memory")
#define CP_WAIT0()  asm volatile("cp.async.wait_group 0;" ::: "memory")

__device__ __forceinline__ float ex2f(float x) {
    float y; asm("ex2.approx.f32 %0, %1;" : "=f"(y) : "f"(x)); return y;
}
// split two fp32 into bf16x2 hi/lo pairs (low half = first element)
__device__ __forceinline__ void split_pack2(float a, float b, uint32_t& hi, uint32_t& lo) {
    __nv_bfloat162 h = __floats2bfloat162_rn(a, b);
    float ra = a - __bfloat162float(h.x);
    float rb = b - __bfloat162float(h.y);
    __nv_bfloat162 l = __floats2bfloat162_rn(ra, rb);
    hi = *(uint32_t*)&h;
    lo = *(uint32_t*)&l;
}

// ---------------------------------------------------------------------------
// Split fp32 -> (bf16 hi, bf16 lo), vectorized x4
// ---------------------------------------------------------------------------
__global__ __launch_bounds__(256) void split_f32_kernel(
    const float* __restrict__ in, __nv_bfloat16* __restrict__ hi,
    __nv_bfloat16* __restrict__ lo, int n4)
{
    int i = blockIdx.x * 256 + threadIdx.x;
    if (i >= n4) return;
    float4 v = ((const float4*)in)[i];
    uint32_t h0, l0, h1, l1;
    split_pack2(v.x, v.y, h0, l0);
    split_pack2(v.z, v.w, h1, l1);
    uint32_t* H = (uint32_t*)hi;
    uint32_t* L = (uint32_t*)lo;
    H[2*i]   = h0;  H[2*i+1] = h1;
    L[2*i]   = l0;  L[2*i+1] = l1;
}

// ---------------------------------------------------------------------------
// QKV weight conversion: W[h][d][k] -> B[n][d], split
// ---------------------------------------------------------------------------
__global__ __launch_bounds__(256) void conv_wqkv_kernel(
    const float* __restrict__ Wq, const float* __restrict__ Wk, const float* __restrict__ Wv,
    __nv_bfloat16* __restrict__ Bh, __nv_bfloat16* __restrict__ Bl)
{
    const int bx = blockIdx.x;
    const int which = bx >> 8;
    const int h = (bx >> 4) & 15;
    const int d0 = (bx & 15) * 64;
    const float* W = (which == 0) ? Wq : (which == 1) ? Wk : Wv;
    __shared__ float tile[64][65];
    const int tid = threadIdx.x;
    #pragma unroll
    for (int it = 0; it < 16; it++) {
        int r = it * 4 + (tid >> 6);
        int c = tid & 63;
        tile[r][c] = W[((size_t)h * 1024 + d0 + r) * 64 + c];
    }
    __syncthreads();
    #pragma unroll
    for (int it = 0; it < 16; it++) {
        int cc = it * 4 + (tid >> 6);
        int dd = tid & 63;
        float v = tile[dd][cc];
        __nv_bfloat16 hh = __float2bfloat16(v);
        __nv_bfloat16 ll = __float2bfloat16(v - __bfloat162float(hh));
        size_t n = (size_t)which * 1024 + h * 64 + cc;
        Bh[n * 1024 + d0 + dd] = hh;
        Bl[n * 1024 + d0 + dd] = ll;
    }
}

// Wo conversion: Wo[k][n] -> B[n][k], split.
__global__ __launch_bounds__(256) void conv_wo_kernel(
    const float* __restrict__ Wo, __nv_bfloat16* __restrict__ Bh, __nv_bfloat16* __restrict__ Bl)
{
    const int bx = blockIdx.x;
    const int k0 = (bx & 15) * 64;
    const int n0 = (bx >> 4) * 64;
    __shared__ float tile[64][65];
    const int tid = threadIdx.x;
    #pragma unroll
    for (int it = 0; it < 16; it++) {
        int r = it * 4 + (tid >> 6);
        int c = tid & 63;
        tile[r][c] = Wo[(size_t)(k0 + r) * 1024 + n0 + c];
    }
    __syncthreads();
    #pragma unroll
    for (int it = 0; it < 16; it++) {
        int cc = it * 4 + (tid >> 6);
        int dd = tid & 63;
        float v = tile[dd][cc];
        __nv_bfloat16 hh = __float2bfloat16(v);
        __nv_bfloat16 ll = __float2bfloat16(v - __bfloat162float(hh));
        Bh[(size_t)(n0 + cc) * 1024 + k0 + dd] = hh;
        Bl[(size_t)(n0 + cc) * 1024 + k0 + dd] = ll;
    }
}

// ---------------------------------------------------------------------------
// mma.sync split-bf16 GEMM (R10 version — unchanged, best known: 503us).
// block 128x128x32, 128 threads / 4 warps (2x2), 2 CTAs/SM.
// ---------------------------------------------------------------------------
#define BM 128
#define BN 128
#define BK 32
#define PADK 40
#define ARR_BYTES (128 * PADK * 2)           // 10240
#define STAGE_BYTES (4 * ARR_BYTES)          // 40960: Ah | Al | Bh | Bl
#define GEMM_SMEM (2 * STAGE_BYTES)          // 81920 -> 2 CTAs/SM

template<int MODE>
__global__ __launch_bounds__(128, 2) void gemm_mma_kernel(
    const __nv_bfloat16* __restrict__ Ah_g, const __nv_bfloat16* __restrict__ Al_g,
    const __nv_bfloat16* __restrict__ Bh_g, const __nv_bfloat16* __restrict__ Bl_g,
    float* __restrict__ out)
{
    extern __shared__ char smc[];
    const int tid = threadIdx.x;
    const int lane = tid & 31;
    const int warp = tid >> 5;       // 0..3
    const int wm = warp >> 1;        // 0..1 -> 64-row band
    const int wn = warp & 1;         // 0..1 -> 64-col band
    const int n0 = blockIdx.x * BN;
    const int t0 = blockIdx.y * BM;
    const uint32_t smem_base = smem_u32(smc);

    auto prefetch = [&](int s, int k0) {
        const uint32_t sbase = smem_base + s * STAGE_BYTES;
        #pragma unroll
        for (int i = 0; i < 16; i++) {
            const int cid = i * 128 + tid;
            const int arr = cid >> 9;
            const int idx = cid & 511;
            const int row = idx >> 2;
            const int c16 = idx & 3;
            const __nv_bfloat16* g;
            if      (arr == 0) g = Ah_g + (size_t)(t0 + row) * DMODEL + k0 + c16 * 8;
            else if (arr == 1) g = Al_g + (size_t)(t0 + row) * DMODEL + k0 + c16 * 8;
            else if (arr == 2) g = Bh_g + (size_t)(n0 + row) * DMODEL + k0 + c16 * 8;
            else               g = Bl_g + (size_t)(n0 + row) * DMODEL + k0 + c16 * 8;
            const uint32_t sa = sbase + arr * ARR_BYTES + (row * PADK + c16 * 8) * 2;
            CP_ASYNC16(sa, g);
        }
        CP_COMMIT();
    };

    float acc[4][8][4];
    #pragma unroll
    for (int i = 0; i < 4; i++)
        #pragma unroll
        for (int j = 0; j < 8; j++)
            #pragma unroll
            for (int q = 0; q < 4; q++) acc[i][j][q] = 0.0f;

    prefetch(0, 0);

    const int r_in = lane & 15;
    const int khalf = (lane >> 4) * 8;

    for (int kt = 0; kt < DMODEL / BK; kt++) {
        if (kt < DMODEL / BK - 1) { prefetch((kt + 1) & 1, (kt + 1) * BK); CP_WAIT1(); }
        else CP_WAIT0();
        __syncthreads();

        const uint32_t sbase = smem_base + (kt & 1) * STAGE_BYTES;
        const uint32_t aH = sbase;
        const uint32_t aL = sbase + ARR_BYTES;
        const uint32_t bH = sbase + 2 * ARR_BYTES;
        const uint32_t bL = sbase + 3 * ARR_BYTES;

        #pragma unroll
        for (int kk = 0; kk < BK; kk += 16) {
            uint32_t ah[4][4], al[4][4];
            #pragma unroll
            for (int mt = 0; mt < 4; mt++) {
                const uint32_t off = ((wm * 64 + mt * 16 + r_in) * PADK + kk + khalf) * 2;
                LDMATRIX_X4(ah[mt], aH + off);
                LDMATRIX_X4(al[mt], aL + off);
            }
            #pragma unroll
            for (int ng = 0; ng < 4; ng++) {
                uint32_t bh[4], bl[4];
                const uint32_t off = ((wn * 64 + ng * 16 + r_in) * PADK + kk + khalf) * 2;
                LDMATRIX_X4(bh, bH + off);
                LDMATRIX_X4(bl, bL + off);
                #pragma unroll
                for (int mt = 0; mt < 4; mt++) {
                    #pragma unroll
                    for (int sel = 0; sel < 2; sel++) {
                        const int nt = ng * 2 + sel;
                        MMA16816(acc[mt][nt], ah[mt], bh[sel], bh[sel + 2]);
                        MMA16816(acc[mt][nt], ah[mt], bl[sel], bl[sel + 2]);
                        MMA16816(acc[mt][nt], al[mt], bh[sel], bh[sel + 2]);
                    }
                }
            }
        }
        __syncthreads();
    }

    const int qr = lane >> 2;
    const int qc = (lane & 3) * 2;
    if (MODE == 1) {
        #pragma unroll
        for (int mt = 0; mt < 4; mt++) {
            const int r1 = t0 + wm * 64 + mt * 16 + qr;
            #pragma unroll
            for (int nt = 0; nt < 8; nt++) {
                const int nb = n0 + wn * 64 + nt * 8 + qc;
                *(float2*)&out[(size_t)r1 * DMODEL + nb]       = make_float2(acc[mt][nt][0], acc[mt][nt][1]);
                *(float2*)&out[(size_t)(r1 + 8) * DMODEL + nb] = make_float2(acc[mt][nt][2], acc[mt][nt][3]);
            }
        }
    } else {
        const int bb = t0 >> 11;
        const int s_base = t0 & 2047;
        #pragma unroll
        for (int nt = 0; nt < 8; nt++) {
            const int nb = n0 + wn * 64 + nt * 8;
            const int which = nb >> 10;
            const int rem = nb & 1023;
            const int h = rem >> 6;
            const int k2 = (rem & 63) + qc;
            __nv_bfloat16 *dh, *dl;
            if      (which == 0) { dh = g_Qh; dl = g_Ql; }
            else if (which == 1) { dh = g_Kh; dl = g_Kl; }
            else                 { dh = g_Vh; dl = g_Vl; }
            const size_t hb = (((size_t)bb * NHEADS + h) * SEQ) * DK + k2;
            #pragma unroll
            for (int mt = 0; mt < 4; mt++) {
                const int s1 = s_base + wm * 64 + mt * 16 + qr;
                uint32_t h0, l0, h1, l1;
                split_pack2(acc[mt][nt][0], acc[mt][nt][1], h0, l0);
                split_pack2(acc[mt][nt][2], acc[mt][nt][3], h1, l1);
                *(uint32_t*)&dh[hb + (size_t)s1 * DK]       = h0;
                *(uint32_t*)&dl[hb + (size_t)s1 * DK]       = l0;
                *(uint32_t*)&dh[hb + (size_t)(s1 + 8) * DK] = h1;
                *(uint32_t*)&dl[hb + (size_t)(s1 + 8) * DK] = l1;
            }
        }
    }
}

// ---------------------------------------------------------------------------
// Flash attention via mma.sync split-bf16, BKV=128 (16 tiles): halves the
// per-tile overhead (barriers, shfl reductions, rescales) vs BKV=64.
// Non-pipelined loop (R10 structure — pipelining measured neutral).
// ---------------------------------------------------------------------------
#define BQ 128
#define BKV 128
#define QSTR 72                              // smem row stride (bf16)
#define Q_ARR  (BQ * QSTR * 2)               // 18432
#define KV_ARR (BKV * QSTR * 2)              // 18432
#define KV_STAGE (4 * KV_ARR)                // 73728 : Kh | Kl | Vh | Vl
#define ATTN_SMEM (2 * Q_ARR + 2 * KV_STAGE) // 184320

__global__ __launch_bounds__(256) void attn_mma_kernel()
{
    extern __shared__ char smc[];
    const uint32_t sb = smem_u32(smc);
    const int tid = threadIdx.x;
    const int lane = tid & 31;
    const int w = tid >> 5;
    const int q0 = blockIdx.x * BQ;
    const int h = blockIdx.y;
    const int b = blockIdx.z;

    const size_t base = (((size_t)b * NHEADS + h) * SEQ) * DK;
    const __nv_bfloat16* Qh_g = g_Qh + base + (size_t)q0 * DK;
    const __nv_bfloat16* Ql_g = g_Ql + base + (size_t)q0 * DK;
    const __nv_bfloat16* Kh_g = g_Kh + base;
    const __nv_bfloat16* Kl_g = g_Kl + base;
    const __nv_bfloat16* Vh_g = g_Vh + base;
    const __nv_bfloat16* Vl_g = g_Vl + base;
    const uint32_t kvbase = sb + 2 * Q_ARR;

    // Q tile: 2048 16B-chunks (Qh|Ql), 8 per thread
    #pragma unroll
    for (int i = 0; i < 8; i++) {
        const int cid = i * 256 + tid;
        const int arr = cid >> 10;
        const int idx = cid & 1023;
        const int row = idx >> 3;
        const int c = (idx & 7) * 8;
        const __nv_bfloat16* g = (arr ? Ql_g : Qh_g) + (size_t)row * DK + c;
        CP_ASYNC16(sb + arr * Q_ARR + (row * QSTR + c) * 2, g);
    }
    CP_COMMIT();

    // KV stage: 4 arrays x 128 rows x 8 chunks = 4096 chunks, 18 per thread
    // (4096+? 4*128*8 = 4096; 4096/256 = 16 per thread)
    auto pref = [&](int kt) {
        const int s = kt & 1;
        const int kv0 = kt * BKV;
        #pragma unroll
        for (int i = 0; i < 16; i++) {
            const int cid = i * 256 + tid;
            const int arr = cid >> 10;         // 0 Kh, 1 Kl, 2 Vh, 3 Vl (1024 chunks each)
            const int idx = cid & 1023;
            const int row = idx >> 3;          // 0..127
            const int c = (idx & 7) * 8;
            const __nv_bfloat16* g;
            if      (arr == 0) g = Kh_g;
            else if (arr == 1) g = Kl_g;
            else if (arr == 2) g = Vh_g;
            else               g = Vl_g;
            g += (size_t)(kv0 + row) * DK + c;
            CP_ASYNC16(kvbase + s * KV_STAGE + arr * KV_ARR + (row * QSTR + c) * 2, g);
        }
        CP_COMMIT();
    };
    pref(0);
    pref(1);

    CP_WAIT2();          // Q resident (kv0, kv1 may be in flight)
    __syncthreads();

    const int r_in = lane & 15;
    const int khalf = (lane >> 4) * 8;
    const int qr = lane >> 2;
    const int qc = (lane & 3) * 2;

    // Q fragments, register-resident for entire loop
    uint32_t qhf[4][4], qlf[4][4];
    #pragma unroll
    for (int kc = 0; kc < 4; kc++) {
        const uint32_t off = ((w * 16 + r_in) * QSTR + kc * 16 + khalf) * 2;
        LDMATRIX_X4(qhf[kc], sb + off);
        LDMATRIX_X4(qlf[kc], sb + Q_ARR + off);
    }

    float oacc[8][4];
    #pragma unroll
    for (int t = 0; t < 8; t++)
        #pragma unroll
        for (int q = 0; q < 4; q++) oacc[t][q] = 0.0f;
    float m0 = -1e30f, m1 = -1e30f, l0 = 0.0f, l1 = 0.0f;
    const float scale2 = 0.18033688011112042f;   // (1/8)*log2(e)

    const int NT = SEQ / BKV;   // 16
    for (int kt = 0; kt < NT; kt++) {
        if (kt == NT - 1) CP_WAIT0(); else CP_WAIT1();
        __syncthreads();
        const uint32_t stg = kvbase + (kt & 1) * KV_STAGE;

        // ---- S = Q K^T (3-pass split), per-warp 16x128 ----
        float sacc[16][4];
        #pragma unroll
        for (int t = 0; t < 16; t++)
            #pragma unroll
            for (int q = 0; q < 4; q++) sacc[t][q] = 0.0f;

        #pragma unroll
        for (int ng = 0; ng < 8; ng++) {
            #pragma unroll
            for (int kc = 0; kc < 4; kc++) {
                uint32_t khf[4], klf[4];
                const uint32_t off = ((ng * 16 + r_in) * QSTR + kc * 16 + khalf) * 2;
                LDMATRIX_X4(khf, stg + off);
                LDMATRIX_X4(klf, stg + KV_ARR + off);
                #pragma unroll
                for (int sel = 0; sel < 2; sel++) {
                    const int t = ng * 2 + sel;
                    MMA16816(sacc[t], qhf[kc], khf[sel], khf[sel + 2]);
                    MMA16816(sacc[t], qhf[kc], klf[sel], klf[sel + 2]);
                    MMA16816(sacc[t], qlf[kc], khf[sel], khf[sel + 2]);
                }
            }
        }

        // ---- online softmax (base-2 domain) over 128 keys ----
        float mx0 = -1e30f, mx1 = -1e30f;
        #pragma unroll
        for (int t = 0; t < 16; t++) {
            mx0 = fmaxf(mx0, fmaxf(sacc[t][0], sacc[t][1]));
            mx1 = fmaxf(mx1, fmaxf(sacc[t][2], sacc[t][3]));
        }
        mx0 *= scale2; mx1 *= scale2;
        mx0 = fmaxf(mx0, __shfl_xor_sync(0xffffffffu, mx0, 1));
        mx0 = fmaxf(mx0, __shfl_xor_sync(0xffffffffu, mx0, 2));
        mx1 = fmaxf(mx1, __shfl_xor_sync(0xffffffffu, mx1, 1));
        mx1 = fmaxf(mx1, __shfl_xor_sync(0xffffffffu, mx1, 2));
        const float nm0 = fmaxf(m0, mx0);
        const float nm1 = fmaxf(m1, mx1);
        const float c0 = ex2f(m0 - nm0);
        const float c1 = ex2f(m1 - nm1);
        m0 = nm0; m1 = nm1;

        float s0 = 0.0f, s1 = 0.0f;
        #pragma unroll
        for (int t = 0; t < 16; t++) {
            sacc[t][0] = ex2f(fmaf(sacc[t][0], scale2, -m0));
            sacc[t][1] = ex2f(fmaf(sacc[t][1], scale2, -m0));
            sacc[t][2] = ex2f(fmaf(sacc[t][2], scale2, -m1));
            sacc[t][3] = ex2f(fmaf(sacc[t][3], scale2, -m1));
            s0 += sacc[t][0] + sacc[t][1];
            s1 += sacc[t][2] + sacc[t][3];
        }
        s0 += __shfl_xor_sync(0xffffffffu, s0, 1);
        s0 += __shfl_xor_sync(0xffffffffu, s0, 2);
        s1 += __shfl_xor_sync(0xffffffffu, s1, 1);
        s1 += __shfl_xor_sync(0xffffffffu, s1, 2);
        l0 = l0 * c0 + s0;
        l1 = l1 * c1 + s1;
        #pragma unroll
        for (int t = 0; t < 8; t++) {
            oacc[t][0] *= c0; oacc[t][1] *= c0;
            oacc[t][2] *= c1; oacc[t][3] *= c1;
        }

        // ---- O += P V (3-pass split); V B-frags via ldmatrix.trans ----
        #pragma unroll
        for (int sc = 0; sc < 8; sc++) {
            uint32_t phf[4], plf[4];
            split_pack2(sacc[sc*2][0],   sacc[sc*2][1],   phf[0], plf[0]);
            split_pack2(sacc[sc*2][2],   sacc[sc*2][3],   phf[1], plf[1]);
            split_pack2(sacc[sc*2+1][0], sacc[sc*2+1][1], phf[2], plf[2]);
            split_pack2(sacc[sc*2+1][2], sacc[sc*2+1][3], phf[3], plf[3]);
            #pragma unroll
            for (int dg = 0; dg < 4; dg++) {
                uint32_t vhf[4], vlf[4];
                const uint32_t voff = ((sc * 16 + r_in) * QSTR + dg * 16 + khalf) * 2;
                LDMATRIX_X4_TRANS(vhf, stg + 2 * KV_ARR + voff);
                LDMATRIX_X4_TRANS(vlf, stg + 3 * KV_ARR + voff);
                #pragma unroll
                for (int sel = 0; sel < 2; sel++) {
                    const int t = dg * 2 + sel;
                    MMA16816(oacc[t], phf, vhf[2*sel], vhf[2*sel+1]);
                    MMA16816(oacc[t], phf, vlf[2*sel], vlf[2*sel+1]);
                    MMA16816(oacc[t], plf, vhf[2*sel], vhf[2*sel+1]);
                }
            }
        }

        __syncthreads();
        if (kt + 2 < NT) pref(kt + 2);
    }

    // ---- epilogue: normalize, split, write heads [t][h*64+d] ----
    const float inv0 = 1.0f / l0;
    const float inv1 = 1.0f / l1;
    const size_t tg0 = (size_t)(b * SEQ + q0 + w * 16 + qr) * DMODEL + h * DK;
    const size_t tg1 = tg0 + (size_t)8 * DMODEL;
    #pragma unroll
    for (int t = 0; t < 8; t++) {
        const int col = t * 8 + qc;
        uint32_t h0, l0p, h1, l1p;
        split_pack2(oacc[t][0] * inv0, oacc[t][1] * inv0, h0, l0p);
        split_pack2(oacc[t][2] * inv1, oacc[t][3] * inv1, h1, l1p);
        *(uint32_t*)&g_hh[tg0 + col] = h0;
        *(uint32_t*)&g_hl[tg0 + col] = l0p;
        *(uint32_t*)&g_hh[tg1 + col] = h1;
        *(uint32_t*)&g_hl[tg1 + col] = l1p;
    }
}

// ---------------------------------------------------------------------------
extern "C" void kernel_launch(void* const* d_in, const int* in_sizes, int n_in,
                              void* d_out, int out_size)
{
    const float* x  = (const float*)d_in[0];
    const float* Wq = (const float*)d_in[1];
    const float* Wk = (const float*)d_in[2];
    const float* Wv = (const float*)d_in[3];
    const float* Wo = (const float*)d_in[4];
    float* out = (float*)d_out;

    __nv_bfloat16 *xh, *xl, *hh, *hl, *bqh, *bql, *bwh, *bwl;
    cudaGetSymbolAddress((void**)&xh,  g_xh);
    cudaGetSymbolAddress((void**)&xl,  g_xl);
    cudaGetSymbolAddress((void**)&hh,  g_hh);
    cudaGetSymbolAddress((void**)&hl,  g_hl);
    cudaGetSymbolAddress((void**)&bqh, g_Bqh);
    cudaGetSymbolAddress((void**)&bql, g_Bql);
    cudaGetSymbolAddress((void**)&bwh, g_Bwh);
    cudaGetSymbolAddress((void**)&bwl, g_Bwl);

    const int n4 = (TOKENS * DMODEL) / 4;

    // 1) Conversions
    split_f32_kernel<<<n4 / 256, 256>>>(x, xh, xl, n4);
    conv_wqkv_kernel<<<768, 256>>>(Wq, Wk, Wv, bqh, bql);
    conv_wo_kernel<<<256, 256>>>(Wo, bwh, bwl);

    // 2) QKV projection (epilogue emits split-bf16 Q/K/V)
    cudaFuncSetAttribute(gemm_mma_kernel<0>,
                         cudaFuncAttributeMaxDynamicSharedMemorySize, GEMM_SMEM);
    gemm_mma_kernel<0><<<dim3(NQKV / BN, TOKENS / BM), 128, GEMM_SMEM>>>(
        xh, xl, bqh, bql, nullptr);

    // 3) Flash attention on tensor cores (BKV=128; writes heads pre-split)
    cudaFuncSetAttribute(attn_mma_kernel,
                         cudaFuncAttributeMaxDynamicSharedMemorySize, ATTN_SMEM);
    attn_mma_kernel<<<dim3(SEQ / BQ, NHEADS, BATCH), 256, ATTN_SMEM>>>();

    // 4) Output projection
    cudaFuncSetAttribute(gemm_mma_kernel<1>,
                         cudaFuncAttributeMaxDynamicSharedMemorySize, GEMM_SMEM);
    gemm_mma_kernel<1><<<dim3(DMODEL / BN, TOKENS / BM), 128, GEMM_SMEM>>>(
        hh, hl, bwh, bwl, out);
}